// round 17
// baseline (speedup 1.0000x reference)
#include <cuda_runtime.h>
#include <cuda_bf16.h>
#include <math.h>
#include <stdint.h>

#define TT    1024
#define BATCH 1024
#define HDIM  100
#define GDIM  400
#define BPB   8
#define NB1   (BATCH / BPB)
#define NT1   400

typedef unsigned long long u64;
typedef unsigned int u32;

// g_h1 holds PACKED bf16 (hi | lo<<16) of layer-0 hidden states
__device__ u32   g_h1[(size_t)TT * BATCH * HDIM];
__device__ float g_pre1[(size_t)TT * BATCH * GDIM];

__device__ __forceinline__ float sigmf(float x) { return 1.0f / (1.0f + __expf(-x)); }
__device__ __forceinline__ float tanh_fast(float x) {
    float t = __expf(2.0f * x);
    return 1.0f - __fdividef(2.0f, t + 1.0f);
}
__device__ __forceinline__ u64 ffma2(u64 a, u64 b, u64 c) {
    u64 d;
    asm("fma.rn.f32x2 %0, %1, %2, %3;" : "=l"(d) : "l"(a), "l"(b), "l"(c));
    return d;
}
__device__ __forceinline__ float hsum2(u64 v) {
    float lo, hi;
    asm("mov.b64 {%0, %1}, %2;" : "=f"(lo), "=f"(hi) : "l"(v));
    return lo + hi;
}
__device__ __forceinline__ u32 bsplit_pack(float v) {
    __nv_bfloat16 bh = __float2bfloat16(v);
    __nv_bfloat16 bl = __float2bfloat16(v - __bfloat162float(bh));
    return (u32)__bfloat16_as_ushort(bh) | ((u32)__bfloat16_as_ushort(bl) << 16);
}
// warp-level bf16 MMA (sm_80+ baseline — no arch-'a' feature needed)
__device__ __forceinline__ void mma16816(float* acc, const u32* a, const u32* b) {
    asm volatile(
        "mma.sync.aligned.m16n8k16.row.col.f32.bf16.bf16.f32 "
        "{%0,%1,%2,%3}, {%4,%5,%6,%7}, {%8,%9}, {%0,%1,%2,%3};"
        : "+f"(acc[0]), "+f"(acc[1]), "+f"(acc[2]), "+f"(acc[3])
        : "r"(a[0]), "r"(a[1]), "r"(a[2]), "r"(a[3]), "r"(b[0]), "r"(b[1]));
}

// ============================================================================
// Layer-0 recurrence (R5 structure, best measured). h1 stored packed bf16.
// ============================================================================
__global__ void __launch_bounds__(NT1, 1) lstm_layer0_kernel(
    const float* __restrict__ x, const float* __restrict__ Wih,
    const float* __restrict__ Whh, const float* __restrict__ bih,
    const float* __restrict__ bhh)
{
    extern __shared__ float sm[];
    float* sW    = sm;
    float* sWin  = sW + GDIM * HDIM;
    float* sBias = sWin + GDIM * 4;
    float* sH0   = sBias + GDIM;
    float* sH1   = sH0 + BPB * HDIM;

    const int tid = threadIdx.x;
    const int bp  = tid & 3;
    const int j0  = tid >> 2;
    const int b0  = 2 * bp, b1 = b0 + 1;
    const int bg0 = blockIdx.x * BPB;

    for (int lin = tid; lin < GDIM * HDIM; lin += NT1) sW[lin] = Whh[lin];
    for (int lin = tid; lin < GDIM * 3; lin += NT1)
        sWin[(lin / 3) * 4 + (lin % 3)] = Wih[lin];
    for (int lin = tid; lin < GDIM; lin += NT1) sBias[lin] = bih[lin] + bhh[lin];
    for (int lin = tid; lin < BPB * HDIM; lin += NT1) sH0[lin] = 0.0f;
    __syncthreads();

    float bi[4], wi[4][3];
    #pragma unroll
    for (int g = 0; g < 4; g++) {
        bi[g] = sBias[g * HDIM + j0];
        wi[g][0] = sWin[(g * HDIM + j0) * 4 + 0];
        wi[g][1] = sWin[(g * HDIM + j0) * 4 + 1];
        wi[g][2] = sWin[(g * HDIM + j0) * 4 + 2];
    }
    const ulonglong2* wp0 = (const ulonglong2*)(sW + (0 * HDIM + j0) * HDIM);
    const ulonglong2* wp1 = (const ulonglong2*)(sW + (1 * HDIM + j0) * HDIM);
    const ulonglong2* wp2 = (const ulonglong2*)(sW + (2 * HDIM + j0) * HDIM);
    const ulonglong2* wp3 = (const ulonglong2*)(sW + (3 * HDIM + j0) * HDIM);
    const float* xa = x + (size_t)(bg0 + b0) * 3072;
    const float* xb = x + (size_t)(bg0 + b1) * 3072;

    float c0 = 0.0f, c1 = 0.0f;
    float* sHr = sH0;
    float* sHw = sH1;

    for (int t = 0; t < TT; t++) {
        float xa0 = xa[t], xa1 = xa[1024 + t], xa2 = xa[2048 + t];
        float xb0 = xb[t], xb1 = xb[1024 + t], xb2 = xb[2048 + t];

        u64 a00 = 0, a01 = 0, a02 = 0, a03 = 0;
        u64 a10 = 0, a11 = 0, a12 = 0, a13 = 0;
        const ulonglong2* hpa = (const ulonglong2*)(sHr + b0 * HDIM);
        const ulonglong2* hpb = (const ulonglong2*)(sHr + b1 * HDIM);
        #pragma unroll
        for (int k4 = 0; k4 < HDIM / 4; k4++) {
            ulonglong2 ha = hpa[k4];
            ulonglong2 hb = hpb[k4];
            ulonglong2 w;
            w = wp0[k4];
            a00 = ffma2(w.x, ha.x, a00); a00 = ffma2(w.y, ha.y, a00);
            a10 = ffma2(w.x, hb.x, a10); a10 = ffma2(w.y, hb.y, a10);
            w = wp1[k4];
            a01 = ffma2(w.x, ha.x, a01); a01 = ffma2(w.y, ha.y, a01);
            a11 = ffma2(w.x, hb.x, a11); a11 = ffma2(w.y, hb.y, a11);
            w = wp2[k4];
            a02 = ffma2(w.x, ha.x, a02); a02 = ffma2(w.y, ha.y, a02);
            a12 = ffma2(w.x, hb.x, a12); a12 = ffma2(w.y, hb.y, a12);
            w = wp3[k4];
            a03 = ffma2(w.x, ha.x, a03); a03 = ffma2(w.y, ha.y, a03);
            a13 = ffma2(w.x, hb.x, a13); a13 = ffma2(w.y, hb.y, a13);
        }

        float gi0 = hsum2(a00) + bi[0] + wi[0][0]*xa0 + wi[0][1]*xa1 + wi[0][2]*xa2;
        float gf0 = hsum2(a01) + bi[1] + wi[1][0]*xa0 + wi[1][1]*xa1 + wi[1][2]*xa2;
        float gg0 = hsum2(a02) + bi[2] + wi[2][0]*xa0 + wi[2][1]*xa1 + wi[2][2]*xa2;
        float go0 = hsum2(a03) + bi[3] + wi[3][0]*xa0 + wi[3][1]*xa1 + wi[3][2]*xa2;
        float gi1 = hsum2(a10) + bi[0] + wi[0][0]*xb0 + wi[0][1]*xb1 + wi[0][2]*xb2;
        float gf1 = hsum2(a11) + bi[1] + wi[1][0]*xb0 + wi[1][1]*xb1 + wi[1][2]*xb2;
        float gg1 = hsum2(a12) + bi[2] + wi[2][0]*xb0 + wi[2][1]*xb1 + wi[2][2]*xb2;
        float go1 = hsum2(a13) + bi[3] + wi[3][0]*xb0 + wi[3][1]*xb1 + wi[3][2]*xb2;

        c0 = sigmf(gf0) * c0 + sigmf(gi0) * tanh_fast(gg0);
        c1 = sigmf(gf1) * c1 + sigmf(gi1) * tanh_fast(gg1);
        float h0 = sigmf(go0) * tanh_fast(c0);
        float h1v = sigmf(go1) * tanh_fast(c1);

        sHw[b0 * HDIM + j0] = h0;
        sHw[b1 * HDIM + j0] = h1v;
        size_t rowbase = ((size_t)t * BATCH + bg0);
        g_h1[(rowbase + b0) * HDIM + j0] = bsplit_pack(h0);
        g_h1[(rowbase + b1) * HDIM + j0] = bsplit_pack(h1v);

        float* tmp = sHr; sHr = sHw; sHw = tmp;
        __syncthreads();
    }
}

// ============================================================================
// Tensor-core GEMM via warp mma.sync bf16 double-split.
// CTA tile 128x80, K=100 pad 112 (7 chunks of k16). 8 warps (4m x 2n),
// warp tile 32x40 = 2x5 m16n8 atoms. Smem holds k-pair-packed u32 tiles.
// pre = Ah*Bh + Ah*Bl + Al*Bh (+bias), fp32 accum.
// ============================================================================
#define PSTR 57            // pair-stride (56 pairs + 1 pad -> de-banked)
#define NPAIR 50           // real k-pairs (K=100)
__global__ void __launch_bounds__(256, 2) gemm_ih1_mma_kernel(
    const float* __restrict__ W, const float* __restrict__ bih,
    const float* __restrict__ bhh)
{
    extern __shared__ u32 smu[];
    u32* sAh = smu;                     // 128*57
    u32* sAl = sAh + 128 * PSTR;
    u32* sBh = sAl + 128 * PSTR;        // 80*57
    u32* sBl = sBh + 80 * PSTR;
    float* sBias = (float*)(sBl + 80 * PSTR);   // 80

    const int tid = threadIdx.x;
    const int lane = tid & 31;
    const int wid = tid >> 5;
    const size_t rbase = (size_t)blockIdx.y * 128;
    const int cbase = blockIdx.x * 80;

    // A: unpack packed (hi|lo<<16) elements into k-pair-packed hi/lo tiles
    for (int lin = tid; lin < 128 * NPAIR; lin += 256) {
        int r = lin / NPAIR, kp = lin % NPAIR;
        uint2 p = *(const uint2*)(g_h1 + (rbase + r) * HDIM + 2 * kp);
        sAh[r * PSTR + kp] = (p.x & 0xFFFFu) | (p.y << 16);
        sAl[r * PSTR + kp] = (p.x >> 16) | (p.y & 0xFFFF0000u);
    }
    for (int lin = tid; lin < 128 * 6; lin += 256) {
        int r = lin / 6, kp = NPAIR + lin % 6;
        sAh[r * PSTR + kp] = 0; sAl[r * PSTR + kp] = 0;
    }
    // B: W fp32 -> split -> k-pair-packed hi/lo tiles
    for (int lin = tid; lin < 80 * NPAIR; lin += 256) {
        int r = lin / NPAIR, kp = lin % NPAIR;
        float2 w = *(const float2*)(W + (size_t)(cbase + r) * HDIM + 2 * kp);
        u32 p0 = bsplit_pack(w.x), p1 = bsplit_pack(w.y);
        sBh[r * PSTR + kp] = (p0 & 0xFFFFu) | (p1 << 16);
        sBl[r * PSTR + kp] = (p0 >> 16) | (p1 & 0xFFFF0000u);
    }
    for (int lin = tid; lin < 80 * 6; lin += 256) {
        int r = lin / 6, kp = NPAIR + lin % 6;
        sBh[r * PSTR + kp] = 0; sBl[r * PSTR + kp] = 0;
    }
    if (tid < 80) sBias[tid] = bih[cbase + tid] + bhh[cbase + tid];
    __syncthreads();

    const int m0 = (wid >> 1) * 32;    // warp m origin (0..96)
    const int n0 = (wid & 1) * 40;     // warp n origin (0 or 40)
    const int g = lane >> 2;           // 0..7
    const int t = lane & 3;            // 0..3

    float acc[2][5][4];
    #pragma unroll
    for (int ma = 0; ma < 2; ma++)
        #pragma unroll
        for (int na = 0; na < 5; na++)
            #pragma unroll
            for (int q = 0; q < 4; q++) acc[ma][na][q] = 0.0f;

    #pragma unroll
    for (int pass = 0; pass < 3; pass++) {
        const u32* A = (pass == 2) ? sAl : sAh;
        const u32* B = (pass == 1) ? sBl : sBh;
        #pragma unroll
        for (int kc = 0; kc < 7; kc++) {
            const int P = kc * 8;
            u32 af[2][4];
            #pragma unroll
            for (int ma = 0; ma < 2; ma++) {
                int row = m0 + ma * 16 + g;
                af[ma][0] = A[row * PSTR + P + t];
                af[ma][1] = A[(row + 8) * PSTR + P + t];
                af[ma][2] = A[row * PSTR + P + 4 + t];
                af[ma][3] = A[(row + 8) * PSTR + P + 4 + t];
            }
            u32 bf[5][2];
            #pragma unroll
            for (int na = 0; na < 5; na++) {
                int col = n0 + na * 8 + g;
                bf[na][0] = B[col * PSTR + P + t];
                bf[na][1] = B[col * PSTR + P + 4 + t];
            }
            #pragma unroll
            for (int ma = 0; ma < 2; ma++)
                #pragma unroll
                for (int na = 0; na < 5; na++)
                    mma16816(acc[ma][na], af[ma], bf[na]);
        }
    }

    // epilogue: d regs -> g_pre1 (+bias), float2 stores
    #pragma unroll
    for (int ma = 0; ma < 2; ma++) {
        #pragma unroll
        for (int na = 0; na < 5; na++) {
            int lcol = n0 + na * 8 + t * 2;
            float bx = sBias[lcol], by = sBias[lcol + 1];
            size_t row = rbase + m0 + ma * 16 + g;
            float2 v0 = make_float2(acc[ma][na][0] + bx, acc[ma][na][1] + by);
            float2 v1 = make_float2(acc[ma][na][2] + bx, acc[ma][na][3] + by);
            *(float2*)(g_pre1 + row * GDIM + cbase + lcol) = v0;
            *(float2*)(g_pre1 + (row + 8) * GDIM + cbase + lcol) = v1;
        }
    }
}

// ============================================================================
// Layer-1 recurrence (R5 structure, unchanged) + fused FC.
// ============================================================================
__global__ void __launch_bounds__(NT1, 1) lstm_layer1_kernel(
    const float* __restrict__ Whh, const float* __restrict__ fcw,
    const float* __restrict__ fcb, float* __restrict__ out)
{
    extern __shared__ float sm[];
    float* sW  = sm;
    float* sH0 = sW + GDIM * HDIM;
    float* sH1 = sH0 + BPB * HDIM;

    const int tid = threadIdx.x;
    const int bp  = tid & 3;
    const int j0  = tid >> 2;
    const int b0  = 2 * bp, b1 = b0 + 1;
    const int bg0 = blockIdx.x * BPB;

    for (int lin = tid; lin < GDIM * HDIM; lin += NT1) sW[lin] = Whh[lin];
    for (int lin = tid; lin < BPB * HDIM; lin += NT1) sH0[lin] = 0.0f;
    __syncthreads();

    const ulonglong2* wp0 = (const ulonglong2*)(sW + (0 * HDIM + j0) * HDIM);
    const ulonglong2* wp1 = (const ulonglong2*)(sW + (1 * HDIM + j0) * HDIM);
    const ulonglong2* wp2 = (const ulonglong2*)(sW + (2 * HDIM + j0) * HDIM);
    const ulonglong2* wp3 = (const ulonglong2*)(sW + (3 * HDIM + j0) * HDIM);

    float c0 = 0.0f, c1 = 0.0f;
    float* sHr = sH0;
    float* sHw = sH1;

    for (int t = 0; t < TT; t++) {
        const float* pra = g_pre1 + ((size_t)t * BATCH + bg0 + b0) * GDIM + j0;
        const float* prb = g_pre1 + ((size_t)t * BATCH + bg0 + b1) * GDIM + j0;
        float p00 = pra[0], p01 = pra[HDIM], p02 = pra[2 * HDIM], p03 = pra[3 * HDIM];
        float p10 = prb[0], p11 = prb[HDIM], p12 = prb[2 * HDIM], p13 = prb[3 * HDIM];

        u64 a00 = 0, a01 = 0, a02 = 0, a03 = 0;
        u64 a10 = 0, a11 = 0, a12 = 0, a13 = 0;
        const ulonglong2* hpa = (const ulonglong2*)(sHr + b0 * HDIM);
        const ulonglong2* hpb = (const ulonglong2*)(sHr + b1 * HDIM);
        #pragma unroll
        for (int k4 = 0; k4 < HDIM / 4; k4++) {
            ulonglong2 ha = hpa[k4];
            ulonglong2 hb = hpb[k4];
            ulonglong2 w;
            w = wp0[k4];
            a00 = ffma2(w.x, ha.x, a00); a00 = ffma2(w.y, ha.y, a00);
            a10 = ffma2(w.x, hb.x, a10); a10 = ffma2(w.y, hb.y, a10);
            w = wp1[k4];
            a01 = ffma2(w.x, ha.x, a01); a01 = ffma2(w.y, ha.y, a01);
            a11 = ffma2(w.x, hb.x, a11); a11 = ffma2(w.y, hb.y, a11);
            w = wp2[k4];
            a02 = ffma2(w.x, ha.x, a02); a02 = ffma2(w.y, ha.y, a02);
            a12 = ffma2(w.x, hb.x, a12); a12 = ffma2(w.y, hb.y, a12);
            w = wp3[k4];
            a03 = ffma2(w.x, ha.x, a03); a03 = ffma2(w.y, ha.y, a03);
            a13 = ffma2(w.x, hb.x, a13); a13 = ffma2(w.y, hb.y, a13);
        }

        float gi0 = hsum2(a00) + p00, gf0 = hsum2(a01) + p01;
        float gg0 = hsum2(a02) + p02, go0 = hsum2(a03) + p03;
        float gi1 = hsum2(a10) + p10, gf1 = hsum2(a11) + p11;
        float gg1 = hsum2(a12) + p12, go1 = hsum2(a13) + p13;

        c0 = sigmf(gf0) * c0 + sigmf(gi0) * tanh_fast(gg0);
        c1 = sigmf(gf1) * c1 + sigmf(gi1) * tanh_fast(gg1);
        sHw[b0 * HDIM + j0] = sigmf(go0) * tanh_fast(c0);
        sHw[b1 * HDIM + j0] = sigmf(go1) * tanh_fast(c1);

        float* tmp = sHr; sHr = sHw; sHw = tmp;
        __syncthreads();
    }

    if (tid < BPB * 10) {
        int bb = tid / 10, o = tid % 10;
        float acc = fcb[o];
        const float* wrow = fcw + o * HDIM;
        const float* hrow = sHr + bb * HDIM;
        #pragma unroll 4
        for (int k = 0; k < HDIM; k++) acc = fmaf(wrow[k], hrow[k], acc);
        out[(bg0 + bb) * 10 + o] = acc;
    }
}

// ============================================================================
extern "C" void kernel_launch(void* const* d_in, const int* in_sizes, int n_in,
                              void* d_out, int out_size)
{
    (void)in_sizes; (void)n_in; (void)out_size;
    const float* x    = (const float*)d_in[0];
    const float* Wih0 = (const float*)d_in[1];
    const float* Whh0 = (const float*)d_in[2];
    const float* bih0 = (const float*)d_in[3];
    const float* bhh0 = (const float*)d_in[4];
    const float* Wih1 = (const float*)d_in[5];
    const float* Whh1 = (const float*)d_in[6];
    const float* bih1 = (const float*)d_in[7];
    const float* bhh1 = (const float*)d_in[8];
    const float* fcw  = (const float*)d_in[9];
    const float* fcb  = (const float*)d_in[10];
    float* out = (float*)d_out;

    const size_t smem0 = (size_t)(GDIM * HDIM + GDIM * 4 + GDIM + 2 * BPB * HDIM) * 4;
    const size_t smemG = (size_t)(128 * PSTR * 2 + 80 * PSTR * 2) * 4 + 80 * 4;
    const size_t smem1 = (size_t)(GDIM * HDIM + 2 * BPB * HDIM) * 4;

    cudaFuncSetAttribute(lstm_layer0_kernel, cudaFuncAttributeMaxDynamicSharedMemorySize, (int)smem0);
    cudaFuncSetAttribute(gemm_ih1_mma_kernel, cudaFuncAttributeMaxDynamicSharedMemorySize, (int)smemG);
    cudaFuncSetAttribute(lstm_layer1_kernel, cudaFuncAttributeMaxDynamicSharedMemorySize, (int)smem1);

    lstm_layer0_kernel<<<NB1, NT1, smem0>>>(x, Wih0, Whh0, bih0, bhh0);

    dim3 g2a(GDIM / 80, (TT * BATCH) / 128);   // (5, 8192)
    gemm_ih1_mma_kernel<<<g2a, 256, smemG>>>(Wih1, bih1, bhh1);

    lstm_layer1_kernel<<<NB1, NT1, smem1>>>(Whh1, fcw, fcb, out);
}